// round 1
// baseline (speedup 1.0000x reference)
#include <cuda_runtime.h>

#define NN 8192
#define THREADS 256
#define ROWS_PER_BLOCK 16
#define NBLOCKS (NN / ROWS_PER_BLOCK)   // 512

// Deterministic per-block partials (no atomics -> bitwise stable output).
__device__ float g_rank[NBLOCKS];
__device__ float g_cnt[NBLOCKS];
__device__ float g_reg[NBLOCKS];

__global__ void __launch_bounds__(THREADS)
svm_pair_kernel(const float* __restrict__ pred,
                const float* __restrict__ target)
{
    extern __shared__ float sh[];      // [2*NN] dynamic: p then t
    float* s_p = sh;
    float* s_t = sh + NN;

    for (int j = threadIdx.x; j < NN; j += THREADS) {
        s_p[j] = pred[j];
        s_t[j] = target[2 * j];        // time
    }
    __syncthreads();

    const int i0 = blockIdx.x * ROWS_PER_BLOCK;

    // Regression term: ROWS_PER_BLOCK rows handled by the first threads.
    float reg_acc = 0.f;
    if (threadIdx.x < ROWS_PER_BLOCK) {
        const int i = i0 + threadIdx.x;
        const float e = target[2 * i + 1];
        float d = s_p[i] - s_t[i];
        if (e == 0.f) d = fmaxf(d, 0.f);
        reg_acc = d * d;
    }

    // Ranking term.
    float rank_acc = 0.f;
    int   cnt_acc  = 0;

    for (int r = 0; r < ROWS_PER_BLOCK; ++r) {
        const int i = i0 + r;
        const float e = target[2 * i + 1];
        if (e == 0.f) continue;        // mask requires event[i]==1
        const float ti = s_t[i];
        const float c  = 1.0f + s_p[i];
        #pragma unroll 8
        for (int j = threadIdx.x; j < NN; j += THREADS) {
            const float tj = s_t[j];
            const float pj = s_p[j];
            if (tj > ti) {
                const float h = fmaxf(c - pj, 0.f);
                rank_acc = fmaf(h, h, rank_acc);
                cnt_acc += 1;
            }
        }
    }

    // Block reduction (shared, deterministic tree).
    __shared__ float red_r[THREADS];
    __shared__ float red_c[THREADS];
    __shared__ float red_g[THREADS];
    red_r[threadIdx.x] = rank_acc;
    red_c[threadIdx.x] = (float)cnt_acc;   // <= 16*8192 = 131072, exact in fp32
    red_g[threadIdx.x] = reg_acc;
    __syncthreads();
    for (int s = THREADS / 2; s > 0; s >>= 1) {
        if (threadIdx.x < s) {
            red_r[threadIdx.x] += red_r[threadIdx.x + s];
            red_c[threadIdx.x] += red_c[threadIdx.x + s];
            red_g[threadIdx.x] += red_g[threadIdx.x + s];
        }
        __syncthreads();
    }
    if (threadIdx.x == 0) {
        g_rank[blockIdx.x] = red_r[0];
        g_cnt[blockIdx.x]  = red_c[0];
        g_reg[blockIdx.x]  = red_g[0];
    }
}

__global__ void svm_final_kernel(float* __restrict__ out)
{
    if (threadIdx.x == 0 && blockIdx.x == 0) {
        double rank = 0.0, cnt = 0.0, reg = 0.0;
        for (int b = 0; b < NBLOCKS; ++b) {
            rank += (double)g_rank[b];
            cnt  += (double)g_cnt[b];
            reg  += (double)g_reg[b];
        }
        if (cnt < 1.0) cnt = 1.0;
        const double R = 0.5;
        const double loss = R * (rank / cnt) + (1.0 - R) * (reg / (double)NN);
        out[0] = (float)loss;
    }
}

extern "C" void kernel_launch(void* const* d_in, const int* in_sizes, int n_in,
                              void* d_out, int out_size)
{
    // Robust input mapping: pred has NN elements, target has 2*NN.
    int pred_idx = 0, tgt_idx = 1;
    if (n_in >= 2 && in_sizes[0] > in_sizes[1]) { pred_idx = 1; tgt_idx = 0; }
    const float* pred   = (const float*)d_in[pred_idx];
    const float* target = (const float*)d_in[tgt_idx];
    float* out = (float*)d_out;

    const size_t shmem = 2 * NN * sizeof(float);  // 64 KB
    static_assert(2 * NN * sizeof(float) == 65536, "");
    cudaFuncSetAttribute(svm_pair_kernel,
                         cudaFuncAttributeMaxDynamicSharedMemorySize,
                         (int)shmem);

    svm_pair_kernel<<<NBLOCKS, THREADS, shmem>>>(pred, target);
    svm_final_kernel<<<1, 32>>>(out);
}

// round 2
// speedup vs baseline: 4.6187x; 4.6187x over previous
#include <cuda_runtime.h>

#define NN 8192
#define THREADS 256
#define ROWS_PER_BLOCK 16
#define NBLOCKS (NN / ROWS_PER_BLOCK)   // 512

// Deterministic per-block partials (no atomics -> bitwise stable output).
__device__ float g_rank[NBLOCKS];
__device__ float g_cnt[NBLOCKS];
__device__ float g_reg[NBLOCKS];

__global__ void __launch_bounds__(THREADS)
svm_pair_kernel(const float* __restrict__ pred,
                const float* __restrict__ target)
{
    extern __shared__ float sh[];      // [2*NN] dynamic: p then t
    float* s_p = sh;
    float* s_t = sh + NN;

    for (int j = threadIdx.x; j < NN; j += THREADS) {
        s_p[j] = pred[j];
        s_t[j] = target[2 * j];        // time
    }
    __syncthreads();

    const int i0 = blockIdx.x * ROWS_PER_BLOCK;

    // Regression term: ROWS_PER_BLOCK rows handled by the first threads.
    float reg_acc = 0.f;
    if (threadIdx.x < ROWS_PER_BLOCK) {
        const int i = i0 + threadIdx.x;
        const float e = target[2 * i + 1];
        float d = s_p[i] - s_t[i];
        if (e == 0.f) d = fmaxf(d, 0.f);
        reg_acc = d * d;
    }

    // Ranking term.
    float rank_acc = 0.f;
    int   cnt_acc  = 0;

    for (int r = 0; r < ROWS_PER_BLOCK; ++r) {
        const int i = i0 + r;
        const float e = target[2 * i + 1];
        if (e == 0.f) continue;        // mask requires event[i]==1
        const float ti = s_t[i];
        const float c  = 1.0f + s_p[i];
        #pragma unroll 8
        for (int j = threadIdx.x; j < NN; j += THREADS) {
            const float tj = s_t[j];
            const float pj = s_p[j];
            const bool m = (tj > ti);
            const float h = m ? fmaxf(c - pj, 0.f) : 0.f;
            rank_acc = fmaf(h, h, rank_acc);
            cnt_acc += m ? 1 : 0;
        }
    }

    // Block reduction (shared, deterministic tree).
    __shared__ float red_r[THREADS];
    __shared__ float red_c[THREADS];
    __shared__ float red_g[THREADS];
    red_r[threadIdx.x] = rank_acc;
    red_c[threadIdx.x] = (float)cnt_acc;   // <= 16*8192 = 131072, exact in fp32
    red_g[threadIdx.x] = reg_acc;
    __syncthreads();
    for (int s = THREADS / 2; s > 0; s >>= 1) {
        if (threadIdx.x < s) {
            red_r[threadIdx.x] += red_r[threadIdx.x + s];
            red_c[threadIdx.x] += red_c[threadIdx.x + s];
            red_g[threadIdx.x] += red_g[threadIdx.x + s];
        }
        __syncthreads();
    }
    if (threadIdx.x == 0) {
        g_rank[blockIdx.x] = red_r[0];
        g_cnt[blockIdx.x]  = red_c[0];
        g_reg[blockIdx.x]  = red_g[0];
    }
}

// Parallel deterministic final combine: 256 threads, each sums 2 partials,
// then a shared-memory tree reduction in double.
__global__ void __launch_bounds__(THREADS)
svm_final_kernel(float* __restrict__ out)
{
    __shared__ double sr[THREADS];
    __shared__ double sc[THREADS];
    __shared__ double sg[THREADS];

    const int t = threadIdx.x;
    double rank = 0.0, cnt = 0.0, reg = 0.0;
    #pragma unroll
    for (int k = 0; k < NBLOCKS / THREADS; ++k) {   // 2 iterations
        const int b = t + k * THREADS;
        rank += (double)g_rank[b];
        cnt  += (double)g_cnt[b];
        reg  += (double)g_reg[b];
    }
    sr[t] = rank; sc[t] = cnt; sg[t] = reg;
    __syncthreads();
    #pragma unroll
    for (int s = THREADS / 2; s > 0; s >>= 1) {
        if (t < s) {
            sr[t] += sr[t + s];
            sc[t] += sc[t + s];
            sg[t] += sg[t + s];
        }
        __syncthreads();
    }
    if (t == 0) {
        double c = sc[0];
        if (c < 1.0) c = 1.0;
        const double R = 0.5;
        const double loss = R * (sr[0] / c) + (1.0 - R) * (sg[0] / (double)NN);
        out[0] = (float)loss;
    }
}

extern "C" void kernel_launch(void* const* d_in, const int* in_sizes, int n_in,
                              void* d_out, int out_size)
{
    // Robust input mapping: pred has NN elements, target has 2*NN.
    int pred_idx = 0, tgt_idx = 1;
    if (n_in >= 2 && in_sizes[0] > in_sizes[1]) { pred_idx = 1; tgt_idx = 0; }
    const float* pred   = (const float*)d_in[pred_idx];
    const float* target = (const float*)d_in[tgt_idx];
    float* out = (float*)d_out;

    const size_t shmem = 2 * NN * sizeof(float);  // 64 KB
    static_assert(2 * NN * sizeof(float) == 65536, "");
    cudaFuncSetAttribute(svm_pair_kernel,
                         cudaFuncAttributeMaxDynamicSharedMemorySize,
                         (int)shmem);

    svm_pair_kernel<<<NBLOCKS, THREADS, shmem>>>(pred, target);
    svm_final_kernel<<<1, THREADS>>>(out);
}

// round 3
// speedup vs baseline: 6.2591x; 1.3552x over previous
#include <cuda_runtime.h>

#define NN 8192
#define THREADS 256
#define NJ 32                      // j's per thread: 256*32 = 8192
#define GRID 444                   // 148 SMs * 3 CTAs -> exactly one wave

// Deterministic per-block partials.
__device__ float g_rank[GRID];
__device__ float g_cnt[GRID];
__device__ float g_reg[GRID];

__global__ void __launch_bounds__(THREADS)
svm_pair_kernel(const float* __restrict__ pred,
                const float* __restrict__ target)
{
    const int tid = threadIdx.x;

    // Register-resident j data: loaded once, reused for every row.
    float tj[NJ], pjn[NJ];
    #pragma unroll
    for (int k = 0; k < NJ; ++k) {
        const int j = tid + k * THREADS;
        tj[k]  = target[2 * j];        // time[j]
        pjn[k] = pred[j];              // p[j]
    }

    float r0 = 0.f, r1 = 0.f, r2 = 0.f, r3 = 0.f;
    int   c0 = 0, c1 = 0;
    float reg_acc = 0.f;

    for (int i = blockIdx.x; i < NN; i += GRID) {
        const float ti = target[2 * i];
        const float ei = target[2 * i + 1];
        const float pi = pred[i];

        if (tid == 0) {                // regression term, once per row
            float d = pi - ti;
            if (ei == 0.f) d = fmaxf(d, 0.f);
            reg_acc = fmaf(d, d, reg_acc);
        }

        if (ei != 0.f) {               // uniform branch across block
            const float c = 1.0f + pi;
            #pragma unroll
            for (int k = 0; k < NJ; k += 4) {
                {
                    const bool m = tj[k] > ti;
                    const float h = fmaxf(c - pjn[k], 0.f);
                    if (m) { r0 = fmaf(h, h, r0); c0++; }
                }
                {
                    const bool m = tj[k + 1] > ti;
                    const float h = fmaxf(c - pjn[k + 1], 0.f);
                    if (m) { r1 = fmaf(h, h, r1); c1++; }
                }
                {
                    const bool m = tj[k + 2] > ti;
                    const float h = fmaxf(c - pjn[k + 2], 0.f);
                    if (m) { r2 = fmaf(h, h, r2); c0++; }
                }
                {
                    const bool m = tj[k + 3] > ti;
                    const float h = fmaxf(c - pjn[k + 3], 0.f);
                    if (m) { r3 = fmaf(h, h, r3); c1++; }
                }
            }
        }
    }

    const float rank_acc = (r0 + r1) + (r2 + r3);
    const int   cnt_acc  = c0 + c1;

    // Block reduction (shared tree, deterministic).
    __shared__ float red_r[THREADS];
    __shared__ float red_c[THREADS];
    __shared__ float red_g[THREADS];
    red_r[tid] = rank_acc;
    red_c[tid] = (float)cnt_acc;       // <= 19*32 per thread; block sum < 2^24
    red_g[tid] = reg_acc;
    __syncthreads();
    #pragma unroll
    for (int s = THREADS / 2; s > 0; s >>= 1) {
        if (tid < s) {
            red_r[tid] += red_r[tid + s];
            red_c[tid] += red_c[tid + s];
            red_g[tid] += red_g[tid + s];
        }
        __syncthreads();
    }
    if (tid == 0) {
        g_rank[blockIdx.x] = red_r[0];
        g_cnt[blockIdx.x]  = red_c[0];
        g_reg[blockIdx.x]  = red_g[0];
    }
}

// Parallel deterministic final combine.
__global__ void __launch_bounds__(THREADS)
svm_final_kernel(float* __restrict__ out)
{
    __shared__ double sr[THREADS];
    __shared__ double sc[THREADS];
    __shared__ double sg[THREADS];

    const int t = threadIdx.x;
    double rank = 0.0, cnt = 0.0, reg = 0.0;
    for (int b = t; b < GRID; b += THREADS) {   // 2 iterations (444/256)
        rank += (double)g_rank[b];
        cnt  += (double)g_cnt[b];
        reg  += (double)g_reg[b];
    }
    sr[t] = rank; sc[t] = cnt; sg[t] = reg;
    __syncthreads();
    #pragma unroll
    for (int s = THREADS / 2; s > 0; s >>= 1) {
        if (t < s) {
            sr[t] += sr[t + s];
            sc[t] += sc[t + s];
            sg[t] += sg[t + s];
        }
        __syncthreads();
    }
    if (t == 0) {
        double c = sc[0];
        if (c < 1.0) c = 1.0;
        const double R = 0.5;
        const double loss = R * (sr[0] / c) + (1.0 - R) * (sg[0] / (double)NN);
        out[0] = (float)loss;
    }
}

extern "C" void kernel_launch(void* const* d_in, const int* in_sizes, int n_in,
                              void* d_out, int out_size)
{
    // Robust input mapping: pred has NN elements, target has 2*NN.
    int pred_idx = 0, tgt_idx = 1;
    if (n_in >= 2 && in_sizes[0] > in_sizes[1]) { pred_idx = 1; tgt_idx = 0; }
    const float* pred   = (const float*)d_in[pred_idx];
    const float* target = (const float*)d_in[tgt_idx];
    float* out = (float*)d_out;

    svm_pair_kernel<<<GRID, THREADS>>>(pred, target);
    svm_final_kernel<<<1, THREADS>>>(out);
}